// round 6
// baseline (speedup 1.0000x reference)
#include <cuda_runtime.h>
#include <cuda.h>
#include <cuda_bf16.h>
#include <cstdint>

#define D_IN 1024
#define H    4096

// ---------------- device scratch ----------------
__device__ __align__(1024) __nv_bfloat16 g_W1sT[D_IN * H];  // [i][h] = bf16(s[h]*W1[h][i])
__device__ __align__(1024) __nv_bfloat16 g_W2h[H * H];      // bf16 copy of W2
__device__ __align__(16) float g_u0[H];
__device__ __align__(16) float g_w[H];
__device__ __align__(16) float g_v0[H];
__device__ __align__(16) float g_t[H];
__device__ __align__(16) float g_part1[H];
__device__ __align__(16) float g_qpart[4 * H];
__device__ unsigned int g_ctrA;   // monotonic epoch counters (never reset)
__device__ unsigned int g_ctrB;

// ---------------- PTX helpers ----------------
__device__ __forceinline__ uint32_t smem_u32(const void* p) {
    uint32_t a;
    asm("{ .reg .u64 t; cvta.to.shared.u64 t, %1; cvt.u32.u64 %0, t; }" : "=r"(a) : "l"(p));
    return a;
}
__device__ __forceinline__ uint32_t elect_one() {
    uint32_t p;
    asm volatile("{ .reg .pred P; elect.sync _|P, 0xFFFFFFFF; selp.b32 %0, 1, 0, P; }" : "=r"(p));
    return p;
}
__device__ __forceinline__ void mbar_init(uint32_t mbar, uint32_t cnt) {
    asm volatile("mbarrier.init.shared.b64 [%0], %1;" :: "r"(mbar), "r"(cnt) : "memory");
}
__device__ __forceinline__ void mbar_expect_tx(uint32_t mbar, uint32_t bytes) {
    asm volatile("mbarrier.arrive.expect_tx.shared.b64 _, [%0], %1;" :: "r"(mbar), "r"(bytes) : "memory");
}
__device__ __forceinline__ void mbar_arrive(uint32_t mbar) {
    asm volatile("mbarrier.arrive.shared.b64 _, [%0];" :: "r"(mbar) : "memory");
}
__device__ __forceinline__ void mbar_wait(uint32_t mbar, uint32_t parity) {
    asm volatile(
        "{\n\t.reg .pred P;\n\t"
        "W%=:\n\t"
        "mbarrier.try_wait.parity.acquire.cta.shared::cta.b64 P, [%0], %1, 0x989680;\n\t"
        "@!P bra W%=;\n\t}"
        :: "r"(mbar), "r"(parity) : "memory");
}
__device__ __forceinline__ void tma2d(uint32_t sdst, const void* map, int cx, int cy, uint32_t mbar) {
    asm volatile(
        "cp.async.bulk.tensor.2d.shared::cta.global.tile.mbarrier::complete_tx::bytes "
        "[%0], [%1, {%2, %3}], [%4];"
        :: "r"(sdst), "l"(map), "r"(cx), "r"(cy), "r"(mbar) : "memory");
}
__device__ __forceinline__ void ldsm4(uint32_t* r, uint32_t addr) {
    asm volatile("ldmatrix.sync.aligned.m8n8.x4.shared.b16 {%0,%1,%2,%3}, [%4];"
                 : "=r"(r[0]), "=r"(r[1]), "=r"(r[2]), "=r"(r[3]) : "r"(addr));
}
__device__ __forceinline__ void mma_bf16(float* c, const uint32_t* a, uint32_t b0, uint32_t b1) {
    asm volatile(
        "mma.sync.aligned.m16n8k16.row.col.f32.bf16.bf16.f32 "
        "{%0,%1,%2,%3}, {%4,%5,%6,%7}, {%8,%9}, {%0,%1,%2,%3};"
        : "+f"(c[0]), "+f"(c[1]), "+f"(c[2]), "+f"(c[3])
        : "r"(a[0]), "r"(a[1]), "r"(a[2]), "r"(a[3]), "r"(b0), "r"(b1));
}
__device__ __forceinline__ uint32_t swz(uint32_t off) { return off ^ ((off >> 3) & 0x70); }

// grid-wide sync, monotonic-epoch (no reset needed across graph replays)
__device__ __forceinline__ void gsync(unsigned int* ctr, unsigned int nctas) {
    __syncthreads();
    __threadfence();
    if (threadIdx.x == 0) {
        unsigned int old = atomicAdd(ctr, 1);
        unsigned int target = (old / nctas + 1) * nctas;
        while (*(volatile unsigned int*)ctr < target) {}
    }
    __syncthreads();
    __threadfence();
}

// ================= kernel A: K1 (layer1 + transpose) ; gsync ; K2 (dual GEMV + bf16) =================
#define RS_STRIDE 1033
#define SMEM_KA (32 * RS_STRIDE * 4)   // 132224 B

__global__ __launch_bounds__(512, 1) void kA(const float* __restrict__ x,
                                             const float* __restrict__ W1,
                                             const float* __restrict__ b1,
                                             const float* __restrict__ W2,
                                             const float* __restrict__ b2) {
    extern __shared__ __align__(16) char smem[];
    float* rs = (float*)smem;   // [32][RS_STRIDE]
    const int tid = threadIdx.x, wid = tid >> 5, lane = tid & 31;
    const int c = blockIdx.x;   // 0..127

    // ---- phase 0: rows c*32 .. c*32+31 of layer 1 ----
    const float4* xv = (const float4*)x;
#pragma unroll
    for (int rep = 0; rep < 2; rep++) {
        int hl = wid * 2 + rep;
        int h = c * 32 + hl;
        const float4* row = (const float4*)(W1 + (size_t)h * D_IN);
        float4 buf[8];
        float dot = 0.f, sq = 0.f;
#pragma unroll
        for (int it = 0; it < 8; it++) {
            float4 wv = row[it * 32 + lane];
            float4 xw = xv[it * 32 + lane];
            buf[it] = wv;
            dot += wv.x * xw.x + wv.y * xw.y + wv.z * xw.z + wv.w * xw.w;
            sq  += wv.x * wv.x + wv.y * wv.y + wv.z * wv.z + wv.w * wv.w;
        }
#pragma unroll
        for (int off = 16; off; off >>= 1) {
            dot += __shfl_down_sync(0xffffffffu, dot, off);
            sq  += __shfl_down_sync(0xffffffffu, sq,  off);
        }
        float sv = 0.f;
        if (lane == 0) {
            float a0 = dot + b1[h];
            float u0 = tanhf(a0);
            sv = 1.f - u0 * u0;
            g_u0[h] = u0;
            g_w[h]  = -2.f * u0 * sv * sq;
        }
        sv = __shfl_sync(0xffffffffu, sv, 0);
        float* dst = rs + hl * RS_STRIDE;
#pragma unroll
        for (int it = 0; it < 8; it++) {
            float4 v = buf[it];
            int i = it * 128 + lane * 4;
            dst[i]     = v.x * sv;
            dst[i + 1] = v.y * sv;
            dst[i + 2] = v.z * sv;
            dst[i + 3] = v.w * sv;
        }
    }
    __syncthreads();
    // transpose-write bf16: W1sT[i][c*32 .. +31]
#pragma unroll
    for (int ii = 0; ii < 2; ii++) {
        int i = tid + ii * 512;
        uint32_t pk[16];
#pragma unroll
        for (int r = 0; r < 16; r++) {
            __nv_bfloat162 p = __floats2bfloat162_rn(rs[(2 * r) * RS_STRIDE + i],
                                                     rs[(2 * r + 1) * RS_STRIDE + i]);
            pk[r] = *(uint32_t*)&p;
        }
        uint4* dst = (uint4*)(g_W1sT + (size_t)i * H + c * 32);
        dst[0] = make_uint4(pk[0], pk[1], pk[2], pk[3]);
        dst[1] = make_uint4(pk[4], pk[5], pk[6], pk[7]);
        dst[2] = make_uint4(pk[8], pk[9], pk[10], pk[11]);
        dst[3] = make_uint4(pk[12], pk[13], pk[14], pk[15]);
    }

    gsync(&g_ctrA, 128);   // u0/w complete everywhere

    // ---- stage u0/w in smem (phase-0 scratch is dead now) ----
    float4* su = (float4*)smem;          // 1024 float4
    float4* sw = su + (H / 4);           // 1024 float4
    {
        const float4* gu = (const float4*)g_u0;
        const float4* gw = (const float4*)g_w;
#pragma unroll
        for (int ii = 0; ii < 2; ii++) {
            int i = tid + ii * 512;
            su[i] = gu[i];
            sw[i] = gw[i];
        }
    }
    __syncthreads();

    // ---- phase 1: rows c*32 .. +31 of W2: dual GEMV + bf16 copy ----
#pragma unroll
    for (int rep = 0; rep < 2; rep++) {
        int j = c * 32 + wid * 2 + rep;
        const float4* row = (const float4*)(W2 + (size_t)j * H);
        __nv_bfloat16* wout = g_W2h + (size_t)j * H;
        float d1 = 0.f, d2 = 0.f;
#pragma unroll 4
        for (int it = 0; it < 32; it++) {
            float4 a = row[it * 32 + lane];
            float4 u = su[it * 32 + lane];
            float4 w = sw[it * 32 + lane];
            d1 += a.x * u.x + a.y * u.y + a.z * u.z + a.w * u.w;
            d2 += a.x * w.x + a.y * w.y + a.z * w.z + a.w * w.w;
            __nv_bfloat162 q0 = __floats2bfloat162_rn(a.x, a.y);
            __nv_bfloat162 q1 = __floats2bfloat162_rn(a.z, a.w);
            uint2 uo; uo.x = *(uint32_t*)&q0; uo.y = *(uint32_t*)&q1;
            *(uint2*)(wout + it * 128 + lane * 4) = uo;
        }
#pragma unroll
        for (int off = 16; off; off >>= 1) {
            d1 += __shfl_down_sync(0xffffffffu, d1, off);
            d2 += __shfl_down_sync(0xffffffffu, d2, off);
        }
        if (lane == 0) {
            float z0 = d1 + b2[j];
            float v0 = tanhf(z0);
            g_v0[j] = v0;
            g_t[j] = 1.f - v0 * v0;
            g_part1[j] = d2;
        }
    }
}

// ================= kernel B: TMA + mma GEMM (64x64 warp tiles) + square-reduce + final reduce =================
#define BM3 128
#define BN3 256
#define KS3 64
#define NST 4
#define A_ST (BM3 * 128)                 // 16 KB
#define B_ST (BN3 * 128)                 // 32 KB
#define B_OFF (NST * A_ST)               // 64 KB
#define TILE_B (B_OFF + NST * B_ST)      // 192 KB
#define STAGE_TX (A_ST + B_ST)
#define KT3 (H / KS3)                    // 64
#define SMEM_KB (TILE_B + 1024)

__global__ __launch_bounds__(288, 1) void kB(const __grid_constant__ CUtensorMap tmA,
                                             const __grid_constant__ CUtensorMap tmB,
                                             const float* __restrict__ W3,
                                             float* __restrict__ out) {
    extern __shared__ __align__(1024) char smem[];
    const int tid = threadIdx.x, wid = tid >> 5, lane = tid & 31;
    const int bn = blockIdx.x, bm = blockIdx.y;
    const uint32_t dyn = smem_u32(smem);
    const uint32_t bar_full = dyn + TILE_B;
    const uint32_t bar_free = dyn + TILE_B + 32;

    if (tid == 0) {
#pragma unroll
        for (int s = 0; s < NST; s++) {
            mbar_init(bar_full + 8 * s, 1);
            mbar_init(bar_free + 8 * s, 8);   // one elected lane per compute warp
        }
    }
    __syncthreads();

    float pm[4][2];
    int warpM = 0, warpN = 0;

    if (wid == 8) {
        // -------- TMA producer warp --------
        if (elect_one()) {
#pragma unroll
            for (int s = 0; s < NST; s++) {
                mbar_expect_tx(bar_full + 8 * s, STAGE_TX);
                tma2d(dyn + s * A_ST, &tmA, s * KS3, bm * BM3, bar_full + 8 * s);
                tma2d(dyn + B_OFF + s * B_ST, &tmB, s * KS3, bn * BN3, bar_full + 8 * s);
            }
            for (int kt = NST; kt < KT3; kt++) {
                const int s = kt & (NST - 1);
                mbar_wait(bar_free + 8 * s, ((kt - NST) >> 2) & 1);
                mbar_expect_tx(bar_full + 8 * s, STAGE_TX);
                tma2d(dyn + s * A_ST, &tmA, kt * KS3, bm * BM3, bar_full + 8 * s);
                tma2d(dyn + B_OFF + s * B_ST, &tmB, kt * KS3, bn * BN3, bar_full + 8 * s);
            }
        }
#pragma unroll
        for (int mi = 0; mi < 4; mi++) pm[mi][0] = pm[mi][1] = 0.f;
    } else {
        // -------- compute warps: 2x4 grid of 64x64 tiles --------
        warpM = wid >> 2;            // 0..1 : 64 rows
        warpN = wid & 3;             // 0..3 : 64 cols
        const int a_row = warpM * 64 + (lane & 15);
        const uint32_t a_kb = (lane >> 4) * 16;
        const int b_row = warpN * 64 + (lane & 7) + ((lane >> 4) << 3);
        const uint32_t b_kb = ((lane >> 3) & 1) * 16;

        float acc[4][8][4];
#pragma unroll
        for (int mi = 0; mi < 4; mi++)
#pragma unroll
            for (int ni = 0; ni < 8; ni++)
#pragma unroll
                for (int r = 0; r < 4; r++) acc[mi][ni][r] = 0.f;

        uint32_t afr[2][4][4], bfr[2][4][4];

        auto load_frags = [&](int buf, uint32_t abase, uint32_t bbase, int ks) {
#pragma unroll
            for (int mi = 0; mi < 4; mi++) {
                uint32_t off = (uint32_t)(a_row + mi * 16) * 128 + ks * 32 + a_kb;
                ldsm4(afr[buf][mi], abase + swz(off));
            }
#pragma unroll
            for (int nb = 0; nb < 4; nb++) {
                uint32_t off = (uint32_t)(b_row + nb * 16) * 128 + ks * 32 + b_kb;
                ldsm4(bfr[buf][nb], bbase + swz(off));
            }
        };

        int cur = 0;
        mbar_wait(bar_full, 0);
        load_frags(0, dyn, dyn + B_OFF, 0);

        for (int kt = 0; kt < KT3; kt++) {
            const int s = kt & (NST - 1);
            const uint32_t abase = dyn + s * A_ST;
            const uint32_t bbase = dyn + B_OFF + s * B_ST;
#pragma unroll
            for (int ks = 0; ks < 4; ks++) {
                if (ks < 3) {
                    load_frags(cur ^ 1, abase, bbase, ks + 1);
                } else {
                    // our last read of stage s smem already happened (ks==2 prefetch)
                    if (lane == 0) mbar_arrive(bar_free + 8 * s);
                    if (kt + 1 < KT3) {
                        const int kn = kt + 1, sn = kn & (NST - 1);
                        mbar_wait(bar_full + 8 * sn, (kn >> 2) & 1);
                        load_frags(cur ^ 1, dyn + sn * A_ST, dyn + B_OFF + sn * B_ST, 0);
                    }
                }
#pragma unroll
                for (int mi = 0; mi < 4; mi++)
#pragma unroll
                    for (int nb = 0; nb < 4; nb++) {
                        mma_bf16(acc[mi][2 * nb],     afr[cur][mi], bfr[cur][nb][0], bfr[cur][nb][1]);
                        mma_bf16(acc[mi][2 * nb + 1], afr[cur][mi], bfr[cur][nb][2], bfr[cur][nb][3]);
                    }
                cur ^= 1;
            }
        }
        // per-thread square-reduce
#pragma unroll
        for (int mi = 0; mi < 4; mi++) {
            float p0 = 0.f, p1 = 0.f;
#pragma unroll
            for (int ni = 0; ni < 8; ni++) {
                p0 += acc[mi][ni][0] * acc[mi][ni][0] + acc[mi][ni][1] * acc[mi][ni][1];
                p1 += acc[mi][ni][2] * acc[mi][ni][2] + acc[mi][ni][3] * acc[mi][ni][3];
            }
            p0 += __shfl_xor_sync(0xffffffffu, p0, 1);
            p0 += __shfl_xor_sync(0xffffffffu, p0, 2);
            p1 += __shfl_xor_sync(0xffffffffu, p1, 1);
            p1 += __shfl_xor_sync(0xffffffffu, p1, 2);
            pm[mi][0] = p0;
            pm[mi][1] = p1;
        }
    }
    __syncthreads();   // all smem tile reads done; safe to reuse smem
    float* qbuf = (float*)smem;   // [4][128]
    if (wid < 8 && (lane & 3) == 0) {
#pragma unroll
        for (int mi = 0; mi < 4; mi++) {
            int row = warpM * 64 + mi * 16 + (lane >> 2);
            qbuf[warpN * 128 + row]     = pm[mi][0];
            qbuf[warpN * 128 + row + 8] = pm[mi][1];
        }
    }
    __syncthreads();
    if (tid < 128) {
        float q = qbuf[tid] + qbuf[128 + tid] + qbuf[256 + tid] + qbuf[384 + tid];
        g_qpart[(size_t)bn * H + bm * BM3 + tid] = q;
    }

    // ---- grid arrive; only CTA(0,0) finishes the reduction ----
    const bool is0 = (bn == 0) && (bm == 0);
    __syncthreads();
    __threadfence();
    if (tid == 0) {
        unsigned int old = atomicAdd(&g_ctrB, 1);
        if (is0) {
            unsigned int target = (old / 128 + 1) * 128;
            while (*(volatile unsigned int*)&g_ctrB < target) {}
        }
    }
    if (!is0) return;
    __syncthreads();
    __threadfence();

    float local = 0.f;
#pragma unroll
    for (int k = 0; k < 16; k++) {
        int j = tid + k * 288;
        if (j < H) {
            float q = g_qpart[j] + g_qpart[H + j] + g_qpart[2 * H + j] + g_qpart[3 * H + j];
            local += W3[j] * g_t[j] * (g_part1[j] - 2.f * g_v0[j] * q);
        }
    }
#pragma unroll
    for (int off = 16; off; off >>= 1) local += __shfl_down_sync(0xffffffffu, local, off);
    float* red = (float*)smem;
    if (lane == 0) red[wid] = local;
    __syncthreads();
    if (tid == 0) {
        float acc = 0.f;
#pragma unroll
        for (int w = 0; w < 9; w++) acc += red[w];
        out[0] = acc;
    }
}

// ---------------- host launch ----------------
typedef CUresult (*EncFnT)(CUtensorMap*, CUtensorMapDataType, cuuint32_t, void*,
                           const cuuint64_t*, const cuuint64_t*, const cuuint32_t*,
                           const cuuint32_t*, CUtensorMapInterleave, CUtensorMapSwizzle,
                           CUtensorMapL2promotion, CUtensorMapFloatOOBfill);

extern "C" void kernel_launch(void* const* d_in, const int* in_sizes, int n_in,
                              void* d_out, int out_size) {
    const float* x  = (const float*)d_in[0];
    const float* W1 = (const float*)d_in[1];
    const float* b1 = (const float*)d_in[2];
    const float* W2 = (const float*)d_in[3];
    const float* b2 = (const float*)d_in[4];
    const float* W3 = (const float*)d_in[5];
    float* out = (float*)d_out;

    EncFnT enc = nullptr;
    cudaDriverEntryPointQueryResult st;
    cudaGetDriverEntryPoint("cuTensorMapEncodeTiled", (void**)&enc, cudaEnableDefault, &st);

    void* w1st_ptr = nullptr;
    void* w2h_ptr  = nullptr;
    cudaGetSymbolAddress(&w1st_ptr, g_W1sT);
    cudaGetSymbolAddress(&w2h_ptr,  g_W2h);

    CUtensorMap tmA{}, tmB{};
    {
        cuuint64_t dims[2] = {(cuuint64_t)H, (cuuint64_t)H};
        cuuint64_t strd[1] = {(cuuint64_t)H * sizeof(__nv_bfloat16)};
        cuuint32_t box[2]  = {KS3, BM3};
        cuuint32_t estr[2] = {1, 1};
        enc(&tmA, CU_TENSOR_MAP_DATA_TYPE_BFLOAT16, 2, w2h_ptr, dims, strd, box, estr,
            CU_TENSOR_MAP_INTERLEAVE_NONE, CU_TENSOR_MAP_SWIZZLE_128B,
            CU_TENSOR_MAP_L2_PROMOTION_L2_128B, CU_TENSOR_MAP_FLOAT_OOB_FILL_NONE);
    }
    {
        cuuint64_t dims[2] = {(cuuint64_t)H, (cuuint64_t)D_IN};
        cuuint64_t strd[1] = {(cuuint64_t)H * sizeof(__nv_bfloat16)};
        cuuint32_t box[2]  = {KS3, BN3};
        cuuint32_t estr[2] = {1, 1};
        enc(&tmB, CU_TENSOR_MAP_DATA_TYPE_BFLOAT16, 2, w1st_ptr, dims, strd, box, estr,
            CU_TENSOR_MAP_INTERLEAVE_NONE, CU_TENSOR_MAP_SWIZZLE_128B,
            CU_TENSOR_MAP_L2_PROMOTION_L2_128B, CU_TENSOR_MAP_FLOAT_OOB_FILL_NONE);
    }

    cudaFuncSetAttribute(kA, cudaFuncAttributeMaxDynamicSharedMemorySize, SMEM_KA);
    cudaFuncSetAttribute(kB, cudaFuncAttributeMaxDynamicSharedMemorySize, SMEM_KB);

    kA<<<128, 512, SMEM_KA>>>(x, W1, b1, W2, b2);
    dim3 gB(D_IN / BN3, H / BM3);   // (4, 32)
    kB<<<gB, 288, SMEM_KB>>>(tmA, tmB, W3, out);
}

// round 7
// speedup vs baseline: 2.4064x; 2.4064x over previous
#include <cuda_runtime.h>
#include <cuda.h>
#include <cuda_bf16.h>
#include <cstdint>

#define D_IN 1024
#define H    4096

// ---------------- device scratch ----------------
__device__ __align__(1024) __nv_bfloat16 g_W1sT[D_IN * H];  // [i][h] = bf16(s[h]*W1[h][i])
__device__ __align__(1024) __nv_bfloat16 g_W2h[H * H];      // bf16 copy of W2
__device__ __align__(16) float g_u0[H];
__device__ __align__(16) float g_w[H];
__device__ __align__(16) float g_v0[H];
__device__ __align__(16) float g_t[H];
__device__ __align__(16) float g_part1[H];
__device__ __align__(16) float g_qpart[4 * H];
__device__ unsigned int g_ctrA;   // monotonic epoch counters (never reset)
__device__ unsigned int g_ctrB;

// ---------------- PTX helpers ----------------
__device__ __forceinline__ uint32_t smem_u32(const void* p) {
    uint32_t a;
    asm("{ .reg .u64 t; cvta.to.shared.u64 t, %1; cvt.u32.u64 %0, t; }" : "=r"(a) : "l"(p));
    return a;
}
__device__ __forceinline__ uint32_t elect_one() {
    uint32_t p;
    asm volatile("{ .reg .pred P; elect.sync _|P, 0xFFFFFFFF; selp.b32 %0, 1, 0, P; }" : "=r"(p));
    return p;
}
__device__ __forceinline__ void mbar_init(uint32_t mbar, uint32_t cnt) {
    asm volatile("mbarrier.init.shared.b64 [%0], %1;" :: "r"(mbar), "r"(cnt) : "memory");
}
__device__ __forceinline__ void mbar_expect_tx(uint32_t mbar, uint32_t bytes) {
    asm volatile("mbarrier.arrive.expect_tx.shared.b64 _, [%0], %1;" :: "r"(mbar), "r"(bytes) : "memory");
}
__device__ __forceinline__ void mbar_arrive(uint32_t mbar) {
    asm volatile("mbarrier.arrive.shared.b64 _, [%0];" :: "r"(mbar) : "memory");
}
__device__ __forceinline__ void mbar_wait(uint32_t mbar, uint32_t parity) {
    asm volatile(
        "{\n\t.reg .pred P;\n\t"
        "W%=:\n\t"
        "mbarrier.try_wait.parity.acquire.cta.shared::cta.b64 P, [%0], %1, 0x989680;\n\t"
        "@!P bra W%=;\n\t}"
        :: "r"(mbar), "r"(parity) : "memory");
}
__device__ __forceinline__ void tma2d(uint32_t sdst, const void* map, int cx, int cy, uint32_t mbar) {
    asm volatile(
        "cp.async.bulk.tensor.2d.shared::cta.global.tile.mbarrier::complete_tx::bytes "
        "[%0], [%1, {%2, %3}], [%4];"
        :: "r"(sdst), "l"(map), "r"(cx), "r"(cy), "r"(mbar) : "memory");
}
__device__ __forceinline__ void ldsm4(uint32_t* r, uint32_t addr) {
    asm volatile("ldmatrix.sync.aligned.m8n8.x4.shared.b16 {%0,%1,%2,%3}, [%4];"
                 : "=r"(r[0]), "=r"(r[1]), "=r"(r[2]), "=r"(r[3]) : "r"(addr));
}
__device__ __forceinline__ void mma_bf16(float* c, const uint32_t* a, uint32_t b0, uint32_t b1) {
    asm volatile(
        "mma.sync.aligned.m16n8k16.row.col.f32.bf16.bf16.f32 "
        "{%0,%1,%2,%3}, {%4,%5,%6,%7}, {%8,%9}, {%0,%1,%2,%3};"
        : "+f"(c[0]), "+f"(c[1]), "+f"(c[2]), "+f"(c[3])
        : "r"(a[0]), "r"(a[1]), "r"(a[2]), "r"(a[3]), "r"(b0), "r"(b1));
}
__device__ __forceinline__ uint32_t swz(uint32_t off) { return off ^ ((off >> 3) & 0x70); }

// grid-wide sync, monotonic-epoch (no reset needed across graph replays)
__device__ __forceinline__ void gsync(unsigned int* ctr, unsigned int nctas) {
    __syncthreads();
    __threadfence();
    if (threadIdx.x == 0) {
        unsigned int old = atomicAdd(ctr, 1);
        unsigned int target = (old / nctas + 1) * nctas;
        while (*(volatile unsigned int*)ctr < target) {}
    }
    __syncthreads();
    __threadfence();
}

// ================= kernel A: K1 (layer1 + transpose) ; gsync ; K2 (dual GEMV + bf16) =================
#define RS_STRIDE 1033
#define SMEM_KA (32 * RS_STRIDE * 4)   // 132224 B

__global__ __launch_bounds__(512, 1) void kA(const float* __restrict__ x,
                                             const float* __restrict__ W1,
                                             const float* __restrict__ b1,
                                             const float* __restrict__ W2,
                                             const float* __restrict__ b2) {
    extern __shared__ __align__(16) char smem[];
    float* rs = (float*)smem;   // [32][RS_STRIDE]
    const int tid = threadIdx.x, wid = tid >> 5, lane = tid & 31;
    const int c = blockIdx.x;   // 0..127

    // ---- phase 0: rows h0, h0+1 of layer 1, interleaved (2x MLP) ----
    const float4* xv = (const float4*)x;
    {
        const int h0 = c * 32 + wid * 2;
        const float4* r0 = (const float4*)(W1 + (size_t)h0 * D_IN);
        const float4* r1 = (const float4*)(W1 + (size_t)(h0 + 1) * D_IN);
        float4 buf0[8], buf1[8];
        float dot0 = 0.f, sq0 = 0.f, dot1 = 0.f, sq1 = 0.f;
#pragma unroll
        for (int it = 0; it < 8; it++) {
            float4 w0 = r0[it * 32 + lane];
            float4 w1 = r1[it * 32 + lane];
            float4 xw = xv[it * 32 + lane];
            buf0[it] = w0; buf1[it] = w1;
            dot0 += w0.x * xw.x + w0.y * xw.y + w0.z * xw.z + w0.w * xw.w;
            sq0  += w0.x * w0.x + w0.y * w0.y + w0.z * w0.z + w0.w * w0.w;
            dot1 += w1.x * xw.x + w1.y * xw.y + w1.z * xw.z + w1.w * xw.w;
            sq1  += w1.x * w1.x + w1.y * w1.y + w1.z * w1.z + w1.w * w1.w;
        }
#pragma unroll
        for (int off = 16; off; off >>= 1) {
            dot0 += __shfl_down_sync(0xffffffffu, dot0, off);
            sq0  += __shfl_down_sync(0xffffffffu, sq0,  off);
            dot1 += __shfl_down_sync(0xffffffffu, dot1, off);
            sq1  += __shfl_down_sync(0xffffffffu, sq1,  off);
        }
        float sv0 = 0.f, sv1 = 0.f;
        if (lane == 0) {
            float a0 = dot0 + b1[h0];
            float u0 = tanhf(a0);
            sv0 = 1.f - u0 * u0;
            g_u0[h0] = u0;
            g_w[h0]  = -2.f * u0 * sv0 * sq0;
            float a1 = dot1 + b1[h0 + 1];
            float u1 = tanhf(a1);
            sv1 = 1.f - u1 * u1;
            g_u0[h0 + 1] = u1;
            g_w[h0 + 1]  = -2.f * u1 * sv1 * sq1;
        }
        sv0 = __shfl_sync(0xffffffffu, sv0, 0);
        sv1 = __shfl_sync(0xffffffffu, sv1, 0);
        float* d0 = rs + (wid * 2) * RS_STRIDE;
        float* d1 = rs + (wid * 2 + 1) * RS_STRIDE;
#pragma unroll
        for (int it = 0; it < 8; it++) {
            int i = it * 128 + lane * 4;
            float4 v0 = buf0[it], v1 = buf1[it];
            d0[i] = v0.x * sv0; d0[i + 1] = v0.y * sv0; d0[i + 2] = v0.z * sv0; d0[i + 3] = v0.w * sv0;
            d1[i] = v1.x * sv1; d1[i + 1] = v1.y * sv1; d1[i + 2] = v1.z * sv1; d1[i + 3] = v1.w * sv1;
        }
    }
    __syncthreads();
    // transpose-write bf16: W1sT[i][c*32 .. +31]
#pragma unroll
    for (int ii = 0; ii < 2; ii++) {
        int i = tid + ii * 512;
        uint32_t pk[16];
#pragma unroll
        for (int r = 0; r < 16; r++) {
            __nv_bfloat162 p = __floats2bfloat162_rn(rs[(2 * r) * RS_STRIDE + i],
                                                     rs[(2 * r + 1) * RS_STRIDE + i]);
            pk[r] = *(uint32_t*)&p;
        }
        uint4* dst = (uint4*)(g_W1sT + (size_t)i * H + c * 32);
        dst[0] = make_uint4(pk[0], pk[1], pk[2], pk[3]);
        dst[1] = make_uint4(pk[4], pk[5], pk[6], pk[7]);
        dst[2] = make_uint4(pk[8], pk[9], pk[10], pk[11]);
        dst[3] = make_uint4(pk[12], pk[13], pk[14], pk[15]);
    }

    gsync(&g_ctrA, 128);   // u0/w complete everywhere

    // ---- stage u0/w in smem (phase-0 scratch is dead now) ----
    float4* su = (float4*)smem;          // 1024 float4
    float4* sw = su + (H / 4);           // 1024 float4
    {
        const float4* gu = (const float4*)g_u0;
        const float4* gw = (const float4*)g_w;
#pragma unroll
        for (int ii = 0; ii < 2; ii++) {
            int i = tid + ii * 512;
            su[i] = gu[i];
            sw[i] = gw[i];
        }
    }
    __syncthreads();

    // ---- phase 1: rows j0, j0+1 of W2, interleaved dual GEMV + bf16 copy ----
    {
        const int j0 = c * 32 + wid * 2;
        const float4* r0 = (const float4*)(W2 + (size_t)j0 * H);
        const float4* r1 = (const float4*)(W2 + (size_t)(j0 + 1) * H);
        __nv_bfloat16* o0 = g_W2h + (size_t)j0 * H;
        __nv_bfloat16* o1 = g_W2h + (size_t)(j0 + 1) * H;
        float d1a = 0.f, d2a = 0.f, d1b = 0.f, d2b = 0.f;
#pragma unroll 8
        for (int it = 0; it < 32; it++) {
            float4 a0 = r0[it * 32 + lane];
            float4 a1 = r1[it * 32 + lane];
            float4 u = su[it * 32 + lane];
            float4 w = sw[it * 32 + lane];
            d1a += a0.x * u.x + a0.y * u.y + a0.z * u.z + a0.w * u.w;
            d2a += a0.x * w.x + a0.y * w.y + a0.z * w.z + a0.w * w.w;
            d1b += a1.x * u.x + a1.y * u.y + a1.z * u.z + a1.w * u.w;
            d2b += a1.x * w.x + a1.y * w.y + a1.z * w.z + a1.w * w.w;
            __nv_bfloat162 p0 = __floats2bfloat162_rn(a0.x, a0.y);
            __nv_bfloat162 p1 = __floats2bfloat162_rn(a0.z, a0.w);
            uint2 ua; ua.x = *(uint32_t*)&p0; ua.y = *(uint32_t*)&p1;
            *(uint2*)(o0 + it * 128 + lane * 4) = ua;
            __nv_bfloat162 p2 = __floats2bfloat162_rn(a1.x, a1.y);
            __nv_bfloat162 p3 = __floats2bfloat162_rn(a1.z, a1.w);
            uint2 ub; ub.x = *(uint32_t*)&p2; ub.y = *(uint32_t*)&p3;
            *(uint2*)(o1 + it * 128 + lane * 4) = ub;
        }
#pragma unroll
        for (int off = 16; off; off >>= 1) {
            d1a += __shfl_down_sync(0xffffffffu, d1a, off);
            d2a += __shfl_down_sync(0xffffffffu, d2a, off);
            d1b += __shfl_down_sync(0xffffffffu, d1b, off);
            d2b += __shfl_down_sync(0xffffffffu, d2b, off);
        }
        if (lane == 0) {
            float z0 = d1a + b2[j0];
            float v0 = tanhf(z0);
            g_v0[j0] = v0;
            g_t[j0] = 1.f - v0 * v0;
            g_part1[j0] = d2a;
            float z1 = d1b + b2[j0 + 1];
            float v1 = tanhf(z1);
            g_v0[j0 + 1] = v1;
            g_t[j0 + 1] = 1.f - v1 * v1;
            g_part1[j0 + 1] = d2b;
        }
    }
}

// ================= kernel B: TMA + mma GEMM (round-5 config: 16 warps, 32x64 tiles) =================
#define BM3 128
#define BN3 256
#define KS3 64
#define NST 4
#define A_ST (BM3 * 128)                 // 16 KB
#define B_ST (BN3 * 128)                 // 32 KB
#define B_OFF (NST * A_ST)               // 64 KB
#define TILE_B (B_OFF + NST * B_ST)      // 192 KB
#define STAGE_TX (A_ST + B_ST)
#define KT3 (H / KS3)                    // 64
#define SMEM_KB (TILE_B + 1024)

__global__ __launch_bounds__(544, 1) void kB(const __grid_constant__ CUtensorMap tmA,
                                             const __grid_constant__ CUtensorMap tmB,
                                             const float* __restrict__ W3,
                                             float* __restrict__ out) {
    extern __shared__ __align__(1024) char smem[];
    const int tid = threadIdx.x, wid = tid >> 5, lane = tid & 31;
    const int bn = blockIdx.x, bm = blockIdx.y;
    const uint32_t dyn = smem_u32(smem);
    const uint32_t bar_full = dyn + TILE_B;
    const uint32_t bar_free = dyn + TILE_B + 32;

    if (tid == 0) {
#pragma unroll
        for (int s = 0; s < NST; s++) {
            mbar_init(bar_full + 8 * s, 1);
            mbar_init(bar_free + 8 * s, 16);
        }
    }
    __syncthreads();

    float pm[2][2];
    int warpM = 0, warpN = 0;

    if (wid == 16) {
        if (elect_one()) {
#pragma unroll
            for (int s = 0; s < NST; s++) {
                mbar_expect_tx(bar_full + 8 * s, STAGE_TX);
                tma2d(dyn + s * A_ST, &tmA, s * KS3, bm * BM3, bar_full + 8 * s);
                tma2d(dyn + B_OFF + s * B_ST, &tmB, s * KS3, bn * BN3, bar_full + 8 * s);
            }
            for (int kt = NST; kt < KT3; kt++) {
                const int s = kt & (NST - 1);
                mbar_wait(bar_free + 8 * s, ((kt - NST) >> 2) & 1);
                mbar_expect_tx(bar_full + 8 * s, STAGE_TX);
                tma2d(dyn + s * A_ST, &tmA, kt * KS3, bm * BM3, bar_full + 8 * s);
                tma2d(dyn + B_OFF + s * B_ST, &tmB, kt * KS3, bn * BN3, bar_full + 8 * s);
            }
        }
        pm[0][0] = pm[0][1] = pm[1][0] = pm[1][1] = 0.f;
    } else {
        warpM = wid >> 2;            // 0..3, 32 rows
        warpN = wid & 3;             // 0..3, 64 cols
        const int a_row = warpM * 32 + (lane & 15);
        const uint32_t a_kb = (lane >> 4) * 16;
        const int b_row = warpN * 64 + (lane & 7) + ((lane >> 4) << 3);
        const uint32_t b_kb = ((lane >> 3) & 1) * 16;

        float acc[2][8][4];
#pragma unroll
        for (int mi = 0; mi < 2; mi++)
#pragma unroll
            for (int ni = 0; ni < 8; ni++)
#pragma unroll
                for (int r = 0; r < 4; r++) acc[mi][ni][r] = 0.f;

        for (int kt = 0; kt < KT3; kt++) {
            const int s = kt & (NST - 1);
            mbar_wait(bar_full + 8 * s, (kt >> 2) & 1);
            const uint32_t abase = dyn + s * A_ST;
            const uint32_t bbase = dyn + B_OFF + s * B_ST;
#pragma unroll
            for (int ks = 0; ks < 4; ks++) {
                uint32_t afr[2][4];
#pragma unroll
                for (int mi = 0; mi < 2; mi++) {
                    uint32_t off = (uint32_t)(a_row + mi * 16) * 128 + ks * 32 + a_kb;
                    ldsm4(afr[mi], abase + swz(off));
                }
                uint32_t bfr[4][4];
#pragma unroll
                for (int nb = 0; nb < 4; nb++) {
                    uint32_t off = (uint32_t)(b_row + nb * 16) * 128 + ks * 32 + b_kb;
                    ldsm4(bfr[nb], bbase + swz(off));
                }
#pragma unroll
                for (int mi = 0; mi < 2; mi++)
#pragma unroll
                    for (int nb = 0; nb < 4; nb++) {
                        mma_bf16(acc[mi][2 * nb],     afr[mi], bfr[nb][0], bfr[nb][1]);
                        mma_bf16(acc[mi][2 * nb + 1], afr[mi], bfr[nb][2], bfr[nb][3]);
                    }
            }
            if (lane == 0) mbar_arrive(bar_free + 8 * s);
        }
        // per-thread square-reduce into pm
#pragma unroll
        for (int mi = 0; mi < 2; mi++) {
            float p0 = 0.f, p1 = 0.f;
#pragma unroll
            for (int ni = 0; ni < 8; ni++) {
                p0 += acc[mi][ni][0] * acc[mi][ni][0] + acc[mi][ni][1] * acc[mi][ni][1];
                p1 += acc[mi][ni][2] * acc[mi][ni][2] + acc[mi][ni][3] * acc[mi][ni][3];
            }
            p0 += __shfl_xor_sync(0xffffffffu, p0, 1);
            p0 += __shfl_xor_sync(0xffffffffu, p0, 2);
            p1 += __shfl_xor_sync(0xffffffffu, p1, 1);
            p1 += __shfl_xor_sync(0xffffffffu, p1, 2);
            pm[mi][0] = p0;
            pm[mi][1] = p1;
        }
    }
    __syncthreads();   // all smem tile reads done; safe to reuse smem
    float* qbuf = (float*)smem;   // [4][128]
    if (wid < 16 && (lane & 3) == 0) {
#pragma unroll
        for (int mi = 0; mi < 2; mi++) {
            int row = warpM * 32 + mi * 16 + (lane >> 2);
            qbuf[warpN * 128 + row]     = pm[mi][0];
            qbuf[warpN * 128 + row + 8] = pm[mi][1];
        }
    }
    __syncthreads();
    if (tid < 128) {
        float q = qbuf[tid] + qbuf[128 + tid] + qbuf[256 + tid] + qbuf[384 + tid];
        g_qpart[(size_t)bn * H + bm * BM3 + tid] = q;
    }

    // ---- grid arrive; only CTA(0,0) finishes the reduction ----
    const bool is0 = (bn == 0) && (bm == 0);
    __syncthreads();
    __threadfence();
    if (tid == 0) {
        unsigned int old = atomicAdd(&g_ctrB, 1);
        if (is0) {
            unsigned int target = (old / 128 + 1) * 128;
            while (*(volatile unsigned int*)&g_ctrB < target) {}
        }
    }
    if (!is0) return;
    __syncthreads();
    __threadfence();

    float local = 0.f;
    if (tid < 512) {
#pragma unroll
        for (int k = 0; k < 8; k++) {
            int j = tid + k * 512;
            float q = g_qpart[j] + g_qpart[H + j] + g_qpart[2 * H + j] + g_qpart[3 * H + j];
            local += W3[j] * g_t[j] * (g_part1[j] - 2.f * g_v0[j] * q);
        }
    }
#pragma unroll
    for (int off = 16; off; off >>= 1) local += __shfl_down_sync(0xffffffffu, local, off);
    float* red = (float*)smem;
    if (lane == 0) red[wid] = local;
    __syncthreads();
    if (tid == 0) {
        float acc = 0.f;
#pragma unroll
        for (int w = 0; w < 17; w++) acc += red[w];
        out[0] = acc;
    }
}

// ---------------- host launch ----------------
typedef CUresult (*EncFnT)(CUtensorMap*, CUtensorMapDataType, cuuint32_t, void*,
                           const cuuint64_t*, const cuuint64_t*, const cuuint32_t*,
                           const cuuint32_t*, CUtensorMapInterleave, CUtensorMapSwizzle,
                           CUtensorMapL2promotion, CUtensorMapFloatOOBfill);

extern "C" void kernel_launch(void* const* d_in, const int* in_sizes, int n_in,
                              void* d_out, int out_size) {
    const float* x  = (const float*)d_in[0];
    const float* W1 = (const float*)d_in[1];
    const float* b1 = (const float*)d_in[2];
    const float* W2 = (const float*)d_in[3];
    const float* b2 = (const float*)d_in[4];
    const float* W3 = (const float*)d_in[5];
    float* out = (float*)d_out;

    EncFnT enc = nullptr;
    cudaDriverEntryPointQueryResult st;
    cudaGetDriverEntryPoint("cuTensorMapEncodeTiled", (void**)&enc, cudaEnableDefault, &st);

    void* w1st_ptr = nullptr;
    void* w2h_ptr  = nullptr;
    cudaGetSymbolAddress(&w1st_ptr, g_W1sT);
    cudaGetSymbolAddress(&w2h_ptr,  g_W2h);

    CUtensorMap tmA{}, tmB{};
    {
        cuuint64_t dims[2] = {(cuuint64_t)H, (cuuint64_t)H};
        cuuint64_t strd[1] = {(cuuint64_t)H * sizeof(__nv_bfloat16)};
        cuuint32_t box[2]  = {KS3, BM3};
        cuuint32_t estr[2] = {1, 1};
        enc(&tmA, CU_TENSOR_MAP_DATA_TYPE_BFLOAT16, 2, w2h_ptr, dims, strd, box, estr,
            CU_TENSOR_MAP_INTERLEAVE_NONE, CU_TENSOR_MAP_SWIZZLE_128B,
            CU_TENSOR_MAP_L2_PROMOTION_L2_128B, CU_TENSOR_MAP_FLOAT_OOB_FILL_NONE);
    }
    {
        cuuint64_t dims[2] = {(cuuint64_t)H, (cuuint64_t)D_IN};
        cuuint64_t strd[1] = {(cuuint64_t)H * sizeof(__nv_bfloat16)};
        cuuint32_t box[2]  = {KS3, BN3};
        cuuint32_t estr[2] = {1, 1};
        enc(&tmB, CU_TENSOR_MAP_DATA_TYPE_BFLOAT16, 2, w1st_ptr, dims, strd, box, estr,
            CU_TENSOR_MAP_INTERLEAVE_NONE, CU_TENSOR_MAP_SWIZZLE_128B,
            CU_TENSOR_MAP_L2_PROMOTION_L2_128B, CU_TENSOR_MAP_FLOAT_OOB_FILL_NONE);
    }

    cudaFuncSetAttribute(kA, cudaFuncAttributeMaxDynamicSharedMemorySize, SMEM_KA);
    cudaFuncSetAttribute(kB, cudaFuncAttributeMaxDynamicSharedMemorySize, SMEM_KB);

    kA<<<128, 512, SMEM_KA>>>(x, W1, b1, W2, b2);
    dim3 gB(D_IN / BN3, H / BM3);   // (4, 32)
    kB<<<gB, 544, SMEM_KB>>>(tmA, tmB, W3, out);
}